// round 2
// baseline (speedup 1.0000x reference)
#include <cuda_runtime.h>
#include <stdint.h>

// Gather: out[r, :] = table[idx[r], :]
// rows = BATCH*NUM_FEATS = 819200, D = 64 floats = 16 float4 per row.
// 16 threads cooperate per row; each thread moves one float4.

#define D_VEC 16            // float4s per row (64 floats)
#define THREADS 256

__global__ __launch_bounds__(THREADS)
void gather_kernel(const int* __restrict__ indices,
                   const float4* __restrict__ table,
                   float4* __restrict__ out,
                   int num_rows)
{
    int t = blockIdx.x * blockDim.x + threadIdx.x;
    int row = t >> 4;          // /16
    int lane = t & 15;         // %16
    if (row >= num_rows) return;

    int idx = __ldg(&indices[row]);
    // table row base in float4 units
    const float4* src = table + (size_t)idx * D_VEC;
    float4* dst = out + (size_t)row * D_VEC;
    dst[lane] = __ldg(&src[lane]);
}

extern "C" void kernel_launch(void* const* d_in, const int* in_sizes, int n_in,
                              void* d_out, int out_size)
{
    const int* indices = (const int*)d_in[0];       // [B*F] int32
    const float4* table = (const float4*)d_in[1];   // [V, 64] f32 as float4
    float4* out = (float4*)d_out;

    int num_rows = in_sizes[0];                     // 819200
    long long total_threads = (long long)num_rows * D_VEC;
    int blocks = (int)((total_threads + THREADS - 1) / THREADS);

    gather_kernel<<<blocks, THREADS>>>(indices, table, out, num_rows);
}

// round 4
// speedup vs baseline: 1.2977x; 1.2977x over previous
#include <cuda_runtime.h>
#include <stdint.h>

// Gather: out[r, :] = table[idx[r], :]
// rows = 819200, D = 64 floats = 16 float4 per row.
// 16 threads cooperate per row; each thread group of 16 handles
// ROWS_PER_THREAD consecutive rows, with all long-latency loads batched
// up-front to maximize memory-level parallelism.

#define D_VEC 16            // float4s per row (64 floats)
#define THREADS 256
#define RPT 4               // rows per 16-thread group iteration

__global__ __launch_bounds__(THREADS)
void gather_kernel(const int* __restrict__ indices,
                   const float4* __restrict__ table,
                   float4* __restrict__ out,
                   int num_rows)
{
    int t = blockIdx.x * blockDim.x + threadIdx.x;
    int lane = t & 15;                 // which float4 within a row
    int rowBase = (t >> 4) * RPT;      // first of RPT consecutive rows

    if (rowBase >= num_rows) return;

    // Fast path: all RPT rows valid (true for all but possibly the last group)
    if (rowBase + RPT <= num_rows) {
        // 1) batch the index loads (independent -> MLP=RPT)
        int idx[RPT];
#pragma unroll
        for (int u = 0; u < RPT; u++)
            idx[u] = __ldg(&indices[rowBase + u]);

        // 2) batch the table loads (independent -> MLP=RPT per thread)
        float4 v[RPT];
#pragma unroll
        for (int u = 0; u < RPT; u++)
            v[u] = __ldg(&table[(size_t)idx[u] * D_VEC + lane]);

        // 3) streaming stores (write-once output; don't pollute L2)
#pragma unroll
        for (int u = 0; u < RPT; u++)
            __stcs(&out[(size_t)(rowBase + u) * D_VEC + lane], v[u]);
    } else {
        // tail
        for (int u = 0; u < RPT; u++) {
            int r = rowBase + u;
            if (r >= num_rows) break;
            int idx = __ldg(&indices[r]);
            float4 v = __ldg(&table[(size_t)idx * D_VEC + lane]);
            __stcs(&out[(size_t)r * D_VEC + lane], v);
        }
    }
}

extern "C" void kernel_launch(void* const* d_in, const int* in_sizes, int n_in,
                              void* d_out, int out_size)
{
    const int* indices = (const int*)d_in[0];       // [B*F] int32
    const float4* table = (const float4*)d_in[1];   // [V, 64] f32 as float4
    float4* out = (float4*)d_out;

    int num_rows = in_sizes[0];                     // 819200
    long long groups = ((long long)num_rows + RPT - 1) / RPT;   // 16-thread groups
    long long total_threads = groups * 16;
    int blocks = (int)((total_threads + THREADS - 1) / THREADS);

    gather_kernel<<<blocks, THREADS>>>(indices, table, out, num_rows);
}